// round 2
// baseline (speedup 1.0000x reference)
#include <cuda_runtime.h>
#include <math.h>

#define BATCH   32
#define LAYERS  32
#define DIM     4096
#define SELK    24
#define NCHOICE 9
#define GS_EPS  1e-10f

// Scratch: per-batch selected window start index (device global — no allocs).
__device__ int g_idx[BATCH];

// Kernel A: one warp, lane b handles batch b.
// Computes argmax(logits + gumbel(noise)) (first-max tie semantics),
// writes g_idx[b] and the one-hot selection_probs tail of out.
__global__ void select_kernel(const float* __restrict__ logits,
                              const float* __restrict__ noise,
                              float* __restrict__ out) {
    const int b = threadIdx.x;
    if (b >= BATCH) return;

    float best = -INFINITY;
    int   bi   = 0;
    #pragma unroll
    for (int c = 0; c < NCHOICE; c++) {
        float u = noise[b * NCHOICE + c];
        float g = -logf(-logf(u + GS_EPS) + GS_EPS);
        float v = logits[c] + g;            // tau=1, softmax monotone -> same argmax
        if (v > best) { best = v; bi = c; }
    }
    g_idx[b] = bi;

    float* probs = out + (size_t)BATCH * SELK * DIM + b * NCHOICE;
    #pragma unroll
    for (int c = 0; c < NCHOICE; c++)
        probs[c] = (c == bi) ? 1.0f : 0.0f;
}

// Kernel B: pure gather-copy. 24*4096 fp32 = 24576 float4 per batch.
// 256 threads * 4 float4 = 1024 float4/block -> 24 blocks per batch.
// 4 independent loads per thread (MLP=4) before any store.
__global__ void copy_kernel(const float* __restrict__ feats,
                            float* __restrict__ out) {
    const int b   = blockIdx.y;
    const int idx = g_idx[b];               // uniform -> one broadcast L2 access/warp

    const float4* __restrict__ src =
        (const float4*)(feats + (size_t)b * LAYERS * DIM + (size_t)idx * DIM);
    float4* __restrict__ dst = (float4*)(out + (size_t)b * SELK * DIM);

    const int base = blockIdx.x * 1024 + threadIdx.x;

    float4 v0 = src[base];
    float4 v1 = src[base + 256];
    float4 v2 = src[base + 512];
    float4 v3 = src[base + 768];

    dst[base]       = v0;
    dst[base + 256] = v1;
    dst[base + 512] = v2;
    dst[base + 768] = v3;
}

extern "C" void kernel_launch(void* const* d_in, const int* in_sizes, int n_in,
                              void* d_out, int out_size) {
    const float* feats  = (const float*)d_in[0];
    const float* logits = (const float*)d_in[1];
    const float* noise  = (const float*)d_in[2];
    float*       out    = (float*)d_out;

    select_kernel<<<1, 32>>>(logits, noise, out);
    copy_kernel<<<dim3(24, BATCH), 256>>>(feats, out);
}

// round 3
// speedup vs baseline: 1.1925x; 1.1925x over previous
#include <cuda_runtime.h>
#include <math.h>

#define BATCH   32
#define LAYERS  32
#define DIM     4096
#define SELK    24
#define NCHOICE 9
#define GS_EPS  1e-10f

#define F4_PER_LAYER (DIM / 4)          // 1024 float4 per layer
// Block = one (batch, layer): 256 threads x 4 float4 = 1024 float4 = one layer.
// Loads are idx-independent and issue immediately; argmax overlaps their latency.

__global__ void fused_kernel(const float4* __restrict__ feats4,
                             const float*  __restrict__ logits,
                             const float*  __restrict__ noise,
                             float* __restrict__ out) {
    const int b = blockIdx.y;
    const int l = blockIdx.x;           // layer 0..31

    // ---- issue feature loads FIRST (no dependency on idx) ----
    const float4* __restrict__ src =
        feats4 + (size_t)b * LAYERS * F4_PER_LAYER + (size_t)l * F4_PER_LAYER;
    const int t = threadIdx.x;
    float4 v0 = src[t];
    float4 v1 = src[t + 256];
    float4 v2 = src[t + 512];
    float4 v3 = src[t + 768];

    // ---- Gumbel argmax, overlapped with load latency (warp 0, lanes 0-8) ----
    __shared__ int s_idx;
    if (t < 32) {
        int   c = t;
        float v = -INFINITY;
        if (c < NCHOICE) {
            float u = noise[b * NCHOICE + c];
            float g = -logf(-logf(u + GS_EPS) + GS_EPS);
            v = logits[c] + g;          // tau=1; softmax monotone -> same argmax
        }
        int bc = c;
        #pragma unroll
        for (int off = 16; off; off >>= 1) {
            float ov = __shfl_down_sync(0xffffffffu, v,  off);
            int   oc = __shfl_down_sync(0xffffffffu, bc, off);
            // first-max tie semantics (lowest index wins), matching jnp.argmax
            if (ov > v || (ov == v && oc < bc)) { v = ov; bc = oc; }
        }
        if (c == 0) s_idx = bc;
    }
    __syncthreads();                    // does NOT drain outstanding LDGs
    const int idx = s_idx;

    // one-hot selection_probs tail (one block per batch)
    if (l == 0 && t < NCHOICE) {
        out[(size_t)BATCH * SELK * DIM + b * NCHOICE + t] =
            (t == idx) ? 1.0f : 0.0f;
    }

    // ---- block-uniform predicated store: keep layer iff idx <= l < idx+SELK ----
    const unsigned rel = (unsigned)(l - idx);
    if (rel < SELK) {
        float4* __restrict__ dst =
            (float4*)out + (size_t)b * SELK * F4_PER_LAYER + (size_t)rel * F4_PER_LAYER;
        dst[t]       = v0;
        dst[t + 256] = v1;
        dst[t + 512] = v2;
        dst[t + 768] = v3;
    }
}

extern "C" void kernel_launch(void* const* d_in, const int* in_sizes, int n_in,
                              void* d_out, int out_size) {
    const float* feats  = (const float*)d_in[0];
    const float* logits = (const float*)d_in[1];
    const float* noise  = (const float*)d_in[2];
    float*       out    = (float*)d_out;

    dim3 grid(LAYERS, BATCH);           // 1024 blocks, one per (layer, batch)
    fused_kernel<<<grid, 256>>>((const float4*)feats, logits, noise, out);
}